// round 1
// baseline (speedup 1.0000x reference)
#include <cuda_runtime.h>

#define BB 16
#define CC 256
#define TT 64
#define VV 25
#define NN 1600  // TT*VV

// ---- scratch (static __device__, allocation-free) ----
__device__ float g_q[BB * CC * NN];   // (B, C, N)  q transposed: q[b, co, n]
__device__ float g_k[BB * CC * NN];   // (B, C, N)
__device__ float g_w[BB * NN];        // per-position value scalar  w[b, m]
__device__ float g_r[BB * NN];        // skip term  x_in @ W4b + b4
__device__ float g_u[CC];             // u = W3^T @ W4a
__device__ float g_c0;                // W4a . b3

// ---------------------------------------------------------------------------
// prep: u[c'] = sum_c W4[c] * W3[c, c'] ;  c0 = sum_c W4[c]*b3[c]
// ---------------------------------------------------------------------------
__global__ void prep_kernel(const float* __restrict__ W3,
                            const float* __restrict__ b3,
                            const float* __restrict__ W4) {
    int c = threadIdx.x;  // 0..255
    float s = 0.f;
    #pragma unroll 8
    for (int cc = 0; cc < CC; ++cc) s += W4[cc] * W3[cc * CC + c];
    g_u[c] = s;
    if (c == 0) {
        float t = 0.f;
        for (int cc = 0; cc < CC; ++cc) t += W4[cc] * b3[cc];
        g_c0 = t;
    }
}

// ---------------------------------------------------------------------------
// wr: w[b,m] = sum_c x[b,c,m]*u[c] + c0 ;  r[b,m] = sum_c x[b,c,m]*W4[C+c] + b4
// one thread per (b,m); x reads coalesced across m.
// ---------------------------------------------------------------------------
__global__ void wr_kernel(const float* __restrict__ x,
                          const float* __restrict__ W4,
                          const float* __restrict__ b4) {
    int idx = blockIdx.x * blockDim.x + threadIdx.x;  // b*N + m
    int b = idx / NN;
    int m = idx - b * NN;
    const float* xb = x + (size_t)b * CC * NN + m;
    const float* W4b = W4 + CC;
    float aw = 0.f, ar = 0.f;
    #pragma unroll 8
    for (int c = 0; c < CC; ++c) {
        float xv = xb[(size_t)c * NN];
        aw += xv * g_u[c];
        ar += xv * W4b[c];
    }
    g_w[idx] = aw + g_c0;
    g_r[idx] = ar + b4[0];
}

// ---------------------------------------------------------------------------
// qk: per batch,  out[b, co, n] = sum_c W[co,c] * x[b,c,n] + bias[co]
// 64x64 output tile per block, 256 threads, 4x4 register micro-tile.
// grid: (N/64, C/64, B*2)   z even -> q (W1,b1), z odd -> k (W2,b2)
// ---------------------------------------------------------------------------
__global__ void __launch_bounds__(256)
qk_kernel(const float* __restrict__ x,
          const float* __restrict__ W1, const float* __restrict__ b1v,
          const float* __restrict__ W2, const float* __restrict__ b2v) {
    int n0  = blockIdx.x * 64;
    int co0 = blockIdx.y * 64;
    int b   = blockIdx.z >> 1;
    int sel = blockIdx.z & 1;
    const float* W    = sel ? W2 : W1;
    const float* bias = sel ? b2v : b1v;
    float* out        = sel ? g_k : g_q;

    __shared__ float Ws[16][68];  // Ws[k][co_local]
    __shared__ float Xs[16][68];  // Xs[k][n_local]

    int tid = threadIdx.x;
    int tx = tid & 15, ty = tid >> 4;
    int wr_row = tid >> 2;         // 0..63 : co_local for W load
    int wr_k4  = (tid & 3) * 4;    // k sub-offset
    int xl_k   = tid >> 4;         // 0..15
    int xl_n   = (tid & 15) * 4;

    float acc[4][4];
    #pragma unroll
    for (int i = 0; i < 4; i++)
        #pragma unroll
        for (int j = 0; j < 4; j++) acc[i][j] = 0.f;

    const float* xb = x + (size_t)b * CC * NN;

    for (int kc = 0; kc < CC; kc += 16) {
        float4 wv = *(const float4*)&W[(co0 + wr_row) * CC + kc + wr_k4];
        float4 xv = *(const float4*)&xb[(size_t)(kc + xl_k) * NN + n0 + xl_n];
        if (kc) __syncthreads();
        Ws[wr_k4 + 0][wr_row] = wv.x;
        Ws[wr_k4 + 1][wr_row] = wv.y;
        Ws[wr_k4 + 2][wr_row] = wv.z;
        Ws[wr_k4 + 3][wr_row] = wv.w;
        *(float4*)&Xs[xl_k][xl_n] = xv;
        __syncthreads();
        #pragma unroll
        for (int kk = 0; kk < 16; ++kk) {
            float a[4], bb[4];
            *(float4*)a  = *(float4*)&Ws[kk][ty * 4];
            *(float4*)bb = *(float4*)&Xs[kk][tx * 4];
            #pragma unroll
            for (int i = 0; i < 4; i++)
                #pragma unroll
                for (int j = 0; j < 4; j++) acc[i][j] += a[i] * bb[j];
        }
    }

    #pragma unroll
    for (int i = 0; i < 4; i++) {
        int co = co0 + ty * 4 + i;
        float bi = bias[co];
        float4 o = make_float4(acc[i][0] + bi, acc[i][1] + bi,
                               acc[i][2] + bi, acc[i][3] + bi);
        *(float4*)&out[((size_t)b * CC + co) * NN + n0 + tx * 4] = o;
    }
}

// ---------------------------------------------------------------------------
// flash: per (b, 64-row n-tile): stream m in 64-tiles,
//   S[n,m] = sum_c q[b,c,n]*k[b,c,m]   (64x64 tile via shared GEMM)
//   online softmax with scalar value w[m]:
//     out[b,n] = (sum_m e^{S-max} * w[m]) / (sum_m e^{S-max}) + r[b,n]
// grid: (N/64, B), 256 threads (16x16), 4x4 per thread.
// ---------------------------------------------------------------------------
__global__ void __launch_bounds__(256)
flash_kernel(float* __restrict__ outp) {
    int b  = blockIdx.y;
    int n0 = blockIdx.x * 64;
    int tid = threadIdx.x;
    int tx = tid & 15, ty = tid >> 4;

    __shared__ float qs[16][68];
    __shared__ float ks[16][68];
    __shared__ float ws[64];

    const float* qb = g_q + (size_t)b * CC * NN;
    const float* kb = g_k + (size_t)b * CC * NN;
    int lk = tid >> 4;           // 0..15
    int ln = (tid & 15) * 4;     // 0..60

    float rmax[4], rl[4], ra[4];
    #pragma unroll
    for (int i = 0; i < 4; i++) { rmax[i] = -3.0e38f; rl[i] = 0.f; ra[i] = 0.f; }

    for (int m0 = 0; m0 < NN; m0 += 64) {
        __syncthreads();  // protect ws/qs/ks vs previous iteration's readers
        if (tid < 64) ws[tid] = g_w[b * NN + m0 + tid];

        float S[4][4];
        #pragma unroll
        for (int i = 0; i < 4; i++)
            #pragma unroll
            for (int j = 0; j < 4; j++) S[i][j] = 0.f;

        for (int kc = 0; kc < CC; kc += 16) {
            float4 qv = *(const float4*)&qb[(size_t)(kc + lk) * NN + n0 + ln];
            float4 kv = *(const float4*)&kb[(size_t)(kc + lk) * NN + m0 + ln];
            if (kc) __syncthreads();
            *(float4*)&qs[lk][ln] = qv;
            *(float4*)&ks[lk][ln] = kv;
            __syncthreads();
            #pragma unroll
            for (int kk = 0; kk < 16; ++kk) {
                float a[4], bb[4];
                *(float4*)a  = *(float4*)&qs[kk][ty * 4];
                *(float4*)bb = *(float4*)&ks[kk][tx * 4];
                #pragma unroll
                for (int i = 0; i < 4; i++)
                    #pragma unroll
                    for (int j = 0; j < 4; j++) S[i][j] += a[i] * bb[j];
            }
        }

        // online softmax update; ws is visible (synced inside kc loop)
        #pragma unroll
        for (int i = 0; i < 4; i++) {
            float tmax = fmaxf(fmaxf(S[i][0], S[i][1]), fmaxf(S[i][2], S[i][3]));
            #pragma unroll
            for (int o = 1; o < 16; o <<= 1)
                tmax = fmaxf(tmax, __shfl_xor_sync(0xffffffffu, tmax, o));
            float nm = fmaxf(rmax[i], tmax);
            float corr = __expf(rmax[i] - nm);
            float p = 0.f, pa = 0.f;
            #pragma unroll
            for (int j = 0; j < 4; j++) {
                float e = __expf(S[i][j] - nm);
                p += e;
                pa += e * ws[tx * 4 + j];
            }
            #pragma unroll
            for (int o = 1; o < 16; o <<= 1) {
                p  += __shfl_xor_sync(0xffffffffu, p, o);
                pa += __shfl_xor_sync(0xffffffffu, pa, o);
            }
            rl[i] = rl[i] * corr + p;
            ra[i] = ra[i] * corr + pa;
            rmax[i] = nm;
        }
    }

    if (tx == 0) {
        #pragma unroll
        for (int i = 0; i < 4; i++) {
            int n = n0 + ty * 4 + i;
            outp[b * NN + n] = ra[i] / rl[i] + g_r[b * NN + n];
        }
    }
}

// ---------------------------------------------------------------------------
extern "C" void kernel_launch(void* const* d_in, const int* in_sizes, int n_in,
                              void* d_out, int out_size) {
    const float* x  = (const float*)d_in[0];
    const float* W1 = (const float*)d_in[1];
    const float* b1 = (const float*)d_in[2];
    const float* W2 = (const float*)d_in[3];
    const float* b2 = (const float*)d_in[4];
    const float* W3 = (const float*)d_in[5];
    const float* b3 = (const float*)d_in[6];
    const float* W4 = (const float*)d_in[7];
    const float* b4 = (const float*)d_in[8];
    float* out = (float*)d_out;

    prep_kernel<<<1, 256>>>(W3, b3, W4);
    wr_kernel<<<(BB * NN) / 256, 256>>>(x, W4, b4);
    qk_kernel<<<dim3(NN / 64, CC / 64, BB * 2), 256>>>(x, W1, b1, W2, b2);
    flash_kernel<<<dim3(NN / 64, BB), 256>>>(out);
}